// round 3
// baseline (speedup 1.0000x reference)
#include <cuda_runtime.h>

// ============================================================================
// SimpleMACELayer on GB300 — Round 1 (SIMT fp32 baseline, fused design)
//
// out[n,o'] = b[o'] + sum_{e: dst(e)=n} v[e,o']
// v[e,o']   = sum_{q,h} u[e,h,q] * M[q,h,o']
// u[e,h,q]  = sum_{i in s1} src[e,h,i] * A[e,q,i]
// A[e,q,i]  = sum_{j in s2} Y[e,j] * cg[i,j,k(q)]
// M[q,h,o'] = sum_o tp_w[p(q),h,o] * W_lin[o', o*16 + k(q)]   (precomputed)
//
// q enumerates (path p, k in s3(p)) pairs: 99 total. K-dim of the big GEMM
// is (q,h) = 6336. All hot data (node_features 5.1MB, M 1.6MB, cg 16KB,
// out 5.1MB) is L2-resident.
// ============================================================================

#define NPATH 23
#define Q_TOTAL 99
#define EPB 64          // edges per block
#define NTHREADS 256

// Paths in the reference's enumeration order (l1 outer, then l2, then l3 asc,
// with |l1-l2|<=l3<=min(l1+l2,3) and (l1+l2+l3) even):
__constant__ int cPL2[NPATH] = {0,1,2,3, 0,1,1,2,2,3, 0,1,1,2,2,3,3, 0,1,2,2,3,3};
__constant__ int cPL3[NPATH] = {0,1,2,3, 1,0,2,1,3,2, 2,1,3,0,2,1,3, 3,2,1,3,0,2};
// Path index ranges per l1 group (paths are contiguous by l1):
__constant__ int cPSTART[5] = {0,4,10,17,23};

// Fused weight tensor M[q][h][o'] : 99*64*64 floats = 1.6 MB scratch.
__device__ float g_M[Q_TOTAL * 64 * 64];

// ----------------------------------------------------------------------------
// Kernel 1: build M[q,h,o'] = sum_o tp_w[p(q),h,o] * W_lin[o', o*16 + k(q)]
// ----------------------------------------------------------------------------
__global__ void build_M_kernel(const float* __restrict__ tw,
                               const float* __restrict__ wlin) {
    int q = blockIdx.x;
    // map q -> (p, global k)
    int p = 0, k0 = 0;
    for (; p < NPATH; ++p) {
        int c = 2 * cPL3[p] + 1;
        if (q < k0 + c) break;
        k0 += c;
    }
    int l3 = cPL3[p];
    int kg = l3 * l3 + (q - k0);

    __shared__ float twS[4096];  // [h][o]
    __shared__ float wlS[4096];  // [o][o']  (o-major so the dot loop is conflict-free)

    for (int i = threadIdx.x; i < 4096; i += blockDim.x)
        twS[i] = tw[p * 4096 + i];
    for (int i = threadIdx.x; i < 4096; i += blockDim.x) {
        int o = i >> 6, op = i & 63;
        wlS[o * 64 + op] = wlin[op * 1024 + o * 16 + kg];
    }
    __syncthreads();

    for (int r = threadIdx.x; r < 4096; r += blockDim.x) {
        int h = r >> 6, op = r & 63;
        float acc = 0.0f;
#pragma unroll 8
        for (int o = 0; o < 64; ++o)
            acc += twS[h * 64 + o] * wlS[o * 64 + op];
        g_M[(q * 64 + h) * 64 + op] = acc;
    }
}

// ----------------------------------------------------------------------------
// Kernel 2: initialize out[n,o'] = b[o']
// ----------------------------------------------------------------------------
__global__ void init_out_kernel(float* __restrict__ out,
                                const float* __restrict__ b, int total) {
    int i = blockIdx.x * blockDim.x + threadIdx.x;
    if (i < total) out[i] = b[i & 63];
}

// ----------------------------------------------------------------------------
// Kernel 3: main edge kernel. One block = 64 edges.
// Per block: compute Y, gather src features (per-l1 column slices),
// stream over the 99 q-steps: A -> Uq -> accumulate V += Uq^T @ M_q.
// Finish with 64 atomicAdds per edge into out[dst].
//
// Dynamic smem layout (bytes):
//   sSrc 7*64*64*4 = 114688   [ic][h][e]
//   sUq  64*64*4   =  16384   [h][e]
//   sMs  64*64*4   =  16384   [h][o']
//   sY   16*64*4   =   4096   [j][e]
//   sA   7*64*4    =   1792   [ic][e]
//   idx  2*64*4    =    512
//   total          = 153856
// ----------------------------------------------------------------------------
__global__ __launch_bounds__(NTHREADS, 1)
void edge_kernel(const float* __restrict__ nf,
                 const float* __restrict__ ev,
                 const int*   __restrict__ ei,
                 const float* __restrict__ cg,
                 float*       __restrict__ out,
                 int E) {
    extern __shared__ float sm[];
    float* sSrc = sm;                    // 7*4096
    float* sUq  = sm + 7 * 4096;        // 4096
    float* sMs  = sUq + 4096;           // 4096
    float* sY   = sMs + 4096;           // 1024
    float* sA   = sY + 1024;            // 448
    int*   sSrcIdx = (int*)(sA + 448);  // 64
    int*   sDstIdx = sSrcIdx + 64;      // 64

    const int tid = threadIdx.x;
    const int e0  = blockIdx.x * EPB;

    // --- Phase 0: per-edge Y + indices ---
    if (tid < EPB) {
        int e = e0 + tid;
        if (e < E) {
            float x = ev[e * 3 + 0];
            float y = ev[e * 3 + 1];
            float z = ev[e * 3 + 2];
            float x2 = x * x, y2 = y * y, z2 = z * z;
            float Y[16];
            Y[0]  = 0.28209479177387814f;
            Y[1]  = 0.4886025119029199f * y;
            Y[2]  = 0.4886025119029199f * z;
            Y[3]  = 0.4886025119029199f * x;
            Y[4]  = 1.0925484305920792f * x * y;
            Y[5]  = 1.0925484305920792f * y * z;
            Y[6]  = 0.31539156525252005f * (3.0f * z2 - 1.0f);
            Y[7]  = 1.0925484305920792f * x * z;
            Y[8]  = 0.5462742152960396f * (x2 - y2);
            Y[9]  = 0.5900435899266435f * y * (3.0f * x2 - y2);
            Y[10] = 2.890611442640554f * x * y * z;
            Y[11] = 0.4570457994644658f * y * (5.0f * z2 - 1.0f);
            Y[12] = 0.3731763325901154f * z * (5.0f * z2 - 3.0f);
            Y[13] = 0.4570457994644658f * x * (5.0f * z2 - 1.0f);
            Y[14] = 1.445305721320277f * z * (x2 - y2);
            Y[15] = 0.5900435899266435f * x * (x2 - 3.0f * y2);
#pragma unroll
            for (int j = 0; j < 16; ++j) sY[j * 64 + tid] = Y[j];
            sSrcIdx[tid] = ei[e];       // src row of edge_index
            sDstIdx[tid] = ei[E + e];   // dst row
        } else {
#pragma unroll
            for (int j = 0; j < 16; ++j) sY[j * 64 + tid] = 0.0f;
            sSrcIdx[tid] = 0;
            sDstIdx[tid] = -1;
        }
    }

    // V accumulators: 4 edges x 4 outputs per thread. 16x16 thread grid.
    float V[16];
#pragma unroll
    for (int i = 0; i < 16; ++i) V[i] = 0.0f;
    const int tx = tid & 15;   // o' group
    const int ty = tid >> 4;   // e group

    __syncthreads();

    int q = 0;
    for (int g = 0; g < 4; ++g) {
        const int nc = 2 * g + 1;
        const int i0 = g * g;

        // --- load src feature slice for this l1 group: sSrc[ic][h][e] ---
        for (int idx = tid; idx < nc * 4096; idx += NTHREADS) {
            int e = idx & 63;
            int rest = idx >> 6;
            int h = rest & 63;
            int ic = rest >> 6;
            sSrc[ic * 4096 + h * 64 + e] =
                __ldg(&nf[(long)sSrcIdx[e] * 1024 + h * 16 + i0 + ic]);
        }
        __syncthreads();

        for (int p = cPSTART[g]; p < cPSTART[g + 1]; ++p) {
            const int l2 = cPL2[p];
            const int l3 = cPL3[p];
            const int j0 = l2 * l2, nj = 2 * l2 + 1;
            const int k00 = l3 * l3, nk = 2 * l3 + 1;

            for (int kl = 0; kl < nk; ++kl, ++q) {
                const int kg = k00 + kl;

                // load M_q tile [h][o'] (16KB, L2-resident, coalesced float4)
                {
                    const float4* gm = (const float4*)(g_M + q * 4096);
                    float4* s4 = (float4*)sMs;
                    for (int i = tid; i < 1024; i += NTHREADS) s4[i] = gm[i];
                }
                // compute A[ic][e] = sum_j Y[j][e] * cg[i0+ic, j0+j, kg]
                for (int idx = tid; idx < nc * 64; idx += NTHREADS) {
                    int ic = idx >> 6, e = idx & 63;
                    float acc = 0.0f;
                    for (int jc = 0; jc < nj; ++jc)
                        acc += sY[(j0 + jc) * 64 + e] *
                               __ldg(&cg[(i0 + ic) * 256 + (j0 + jc) * 16 + kg]);
                    sA[ic * 64 + e] = acc;
                }
                __syncthreads();

                // compute Uq[h][e] = sum_ic sSrc[ic][h][e] * A[ic][e]
#pragma unroll
                for (int r = 0; r < 16; ++r) {
                    int idx = r * NTHREADS + tid;
                    int h = idx >> 6, e = idx & 63;
                    float acc = 0.0f;
                    for (int ic = 0; ic < nc; ++ic)
                        acc += sSrc[ic * 4096 + h * 64 + e] * sA[ic * 64 + e];
                    sUq[h * 64 + e] = acc;
                }
                __syncthreads();

                // GEMM: V[e 4][o' 4] += sum_h Uq[h][e] * Ms[h][o']
#pragma unroll 4
                for (int kk = 0; kk < 64; ++kk) {
                    const float4 u = *reinterpret_cast<const float4*>(
                        sUq + kk * 64 + (ty << 2));
                    const float4 m = *reinterpret_cast<const float4*>(
                        sMs + kk * 64 + (tx << 2));
                    V[0]  += u.x * m.x; V[1]  += u.x * m.y;
                    V[2]  += u.x * m.z; V[3]  += u.x * m.w;
                    V[4]  += u.y * m.x; V[5]  += u.y * m.y;
                    V[6]  += u.y * m.z; V[7]  += u.y * m.w;
                    V[8]  += u.z * m.x; V[9]  += u.z * m.y;
                    V[10] += u.z * m.z; V[11] += u.z * m.w;
                    V[12] += u.w * m.x; V[13] += u.w * m.y;
                    V[14] += u.w * m.z; V[15] += u.w * m.w;
                }
                __syncthreads();
            }
        }
        // last inner __syncthreads() protects sSrc reload
    }

    // --- scatter: atomicAdd into out[dst] ---
#pragma unroll
    for (int a = 0; a < 4; ++a) {
        int e = (ty << 2) + a;
        int d = sDstIdx[e];
        if (d >= 0) {
            float* dst = out + d * 64 + (tx << 2);
            atomicAdd(dst + 0, V[a * 4 + 0]);
            atomicAdd(dst + 1, V[a * 4 + 1]);
            atomicAdd(dst + 2, V[a * 4 + 2]);
            atomicAdd(dst + 3, V[a * 4 + 3]);
        }
    }
}

// ----------------------------------------------------------------------------
extern "C" void kernel_launch(void* const* d_in, const int* in_sizes, int n_in,
                              void* d_out, int out_size) {
    const float* nf   = (const float*)d_in[0];  // node_features
    const float* ev   = (const float*)d_in[1];  // edge_vectors
    const int*   ei   = (const int*)  d_in[2];  // edge_index
    const float* cg   = (const float*)d_in[3];  // gaunt coeffs
    const float* tw   = (const float*)d_in[4];  // tp_weights
    const float* wlin = (const float*)d_in[5];  // W_lin
    const float* bl   = (const float*)d_in[6];  // b_lin
    float* out = (float*)d_out;

    const int E = in_sizes[1] / 3;
    const int N = in_sizes[0] / (64 * 16);

    const int SMEM = 153856;
    cudaFuncSetAttribute(edge_kernel,
                         cudaFuncAttributeMaxDynamicSharedMemorySize, SMEM);

    build_M_kernel<<<Q_TOTAL, 256>>>(tw, wlin);
    init_out_kernel<<<(N * 64 + 255) / 256, 256>>>(out, bl, N * 64);
    edge_kernel<<<(E + EPB - 1) / EPB, NTHREADS, SMEM>>>(nf, ev, ei, cg, out, E);
}

// round 5
// speedup vs baseline: 2.7313x; 2.7313x over previous
#include <cuda_runtime.h>
#include <cstdint>

// ============================================================================
// SimpleMACELayer — Round 4: portable mma.sync tf32 (m16n8k8) tensor path.
// v[e,o'] = sum_{q,h} u[e,h,q]*M[q,h,o'] ; register accumulators per warp.
// u, A via SIMT; M pre-fused by build_M (plain layout, tf32-rounded).
// ============================================================================

#define EPB 128
#define NTHREADS 256
#define Q_TOTAL 99

__constant__ int cGQ0[5] = {0, 16, 40, 71, 99};
__constant__ signed char cQP[Q_TOTAL] = {
    0, 1,1,1, 2,2,2,2,2, 3,3,3,3,3,3,3,
    4,4,4, 5, 6,6,6,6,6, 7,7,7, 8,8,8,8,8,8,8, 9,9,9,9,9,
    10,10,10,10,10, 11,11,11, 12,12,12,12,12,12,12, 13,
    14,14,14,14,14, 15,15,15, 16,16,16,16,16,16,16,
    17,17,17,17,17,17,17, 18,18,18,18,18, 19,19,19,
    20,20,20,20,20,20,20, 21, 22,22,22,22,22};
__constant__ signed char cQKG[Q_TOTAL] = {
    0, 1,2,3, 4,5,6,7,8, 9,10,11,12,13,14,15,
    1,2,3, 0, 4,5,6,7,8, 1,2,3, 9,10,11,12,13,14,15, 4,5,6,7,8,
    4,5,6,7,8, 1,2,3, 9,10,11,12,13,14,15, 0,
    4,5,6,7,8, 1,2,3, 9,10,11,12,13,14,15,
    9,10,11,12,13,14,15, 4,5,6,7,8, 1,2,3,
    9,10,11,12,13,14,15, 0, 4,5,6,7,8};
__constant__ signed char cQJ0[Q_TOTAL] = {
    0, 1,1,1, 4,4,4,4,4, 9,9,9,9,9,9,9,
    0,0,0, 1, 1,1,1,1,1, 4,4,4, 4,4,4,4,4,4,4, 9,9,9,9,9,
    0,0,0,0,0, 1,1,1, 1,1,1,1,1,1,1, 4,
    4,4,4,4,4, 9,9,9, 9,9,9,9,9,9,9,
    0,0,0,0,0,0,0, 1,1,1,1,1, 4,4,4,
    4,4,4,4,4,4,4, 9, 9,9,9,9,9};

// Fused weights M[q][h][o'] (plain, tf32-rounded): 99*64*64 floats = 1.6MB.
__device__ float g_M[Q_TOTAL * 4096];

__device__ __forceinline__ uint32_t tf32r(float x) {
    uint32_t y;
    asm("cvt.rna.tf32.f32 %0, %1;" : "=r"(y) : "f"(x));
    return y;
}
__device__ __forceinline__ void mma8(float* c, const uint32_t* a,
                                     uint32_t b0, uint32_t b1) {
    asm volatile(
        "mma.sync.aligned.m16n8k8.row.col.f32.tf32.tf32.f32 "
        "{%0,%1,%2,%3}, {%4,%5,%6,%7}, {%8,%9}, {%0,%1,%2,%3};"
        : "+f"(c[0]), "+f"(c[1]), "+f"(c[2]), "+f"(c[3])
        : "r"(a[0]), "r"(a[1]), "r"(a[2]), "r"(a[3]), "r"(b0), "r"(b1));
}

// ---------------------------------------------------------------------------
__global__ void build_M_kernel(const float* __restrict__ tw,
                               const float* __restrict__ wlin) {
    int q = blockIdx.x, p = cQP[q], kg = cQKG[q];
    __shared__ float twS[4096], wlS[4096];
    for (int i = threadIdx.x; i < 4096; i += blockDim.x) twS[i] = tw[p * 4096 + i];
    for (int i = threadIdx.x; i < 4096; i += blockDim.x) {
        int o = i >> 6, op = i & 63;
        wlS[o * 64 + op] = wlin[op * 1024 + o * 16 + kg];
    }
    __syncthreads();
    for (int r = threadIdx.x; r < 4096; r += blockDim.x) {
        int h = r >> 6, op = r & 63;
        float acc = 0.0f;
#pragma unroll 8
        for (int o = 0; o < 64; ++o) acc += twS[h * 64 + o] * wlS[o * 64 + op];
        g_M[q * 4096 + h * 64 + op] = __uint_as_float(tf32r(acc));
    }
}

__global__ void init_out_kernel(float* __restrict__ out,
                                const float* __restrict__ b, int total) {
    int i = blockIdx.x * blockDim.x + threadIdx.x;
    if (i < total) out[i] = b[i & 63];
}

// ---------------------------------------------------------------------------
// SMEM float offsets:
//   sSrc 0       (7*128*32 = 28672)       [ic][e][hh]
//   sU   28672   (2 * 128*36 = 9216)      [qslot][e][k], row stride 36
//   sM   37888   (2 * 32*68  = 4352)      [qslot][h][o'], row stride 68
//   sY   42240   (16*128 = 2048)
//   sA   44288   (2*7*128 = 1792)
//   sIdx 46080   (256)
// total 46336 floats = 185344 bytes
#define SU_OFF   28672
#define SM_OFF   37888
#define SY_OFF   42240
#define SA_OFF   44288
#define SIDX_OFF 46080
#define SMEM_TOTAL 185344

__global__ __launch_bounds__(NTHREADS, 1)
void edge_kernel(const float* __restrict__ nf, const float* __restrict__ ev,
                 const int* __restrict__ ei, const float* __restrict__ cg,
                 float* __restrict__ out, int E) {
    extern __shared__ float sm[];
    float* sSrc = sm;
    float* sU = sm + SU_OFF;
    float* sM = sm + SM_OFF;
    float* sY = sm + SY_OFF;
    float* sA = sm + SA_OFF;
    int* sIdx = (int*)(sm + SIDX_OFF);
    const int tid = threadIdx.x;
    const int e0 = blockIdx.x * EPB;

    // ---- Y + indices ----
    if (tid < EPB) {
        int e = e0 + tid;
        if (e < E) {
            float x = ev[e * 3], y = ev[e * 3 + 1], z = ev[e * 3 + 2];
            float x2 = x * x, y2 = y * y, z2 = z * z;
            float Y[16];
            Y[0] = 0.28209479177387814f;
            Y[1] = 0.4886025119029199f * y;
            Y[2] = 0.4886025119029199f * z;
            Y[3] = 0.4886025119029199f * x;
            Y[4] = 1.0925484305920792f * x * y;
            Y[5] = 1.0925484305920792f * y * z;
            Y[6] = 0.31539156525252005f * (3.0f * z2 - 1.0f);
            Y[7] = 1.0925484305920792f * x * z;
            Y[8] = 0.5462742152960396f * (x2 - y2);
            Y[9] = 0.5900435899266435f * y * (3.0f * x2 - y2);
            Y[10] = 2.890611442640554f * x * y * z;
            Y[11] = 0.4570457994644658f * y * (5.0f * z2 - 1.0f);
            Y[12] = 0.3731763325901154f * z * (5.0f * z2 - 3.0f);
            Y[13] = 0.4570457994644658f * x * (5.0f * z2 - 1.0f);
            Y[14] = 1.445305721320277f * z * (x2 - y2);
            Y[15] = 0.5900435899266435f * x * (x2 - 3.0f * y2);
#pragma unroll
            for (int j = 0; j < 16; ++j) sY[j * EPB + tid] = Y[j];
            sIdx[tid] = ei[e];
            sIdx[EPB + tid] = ei[E + e];
        } else {
#pragma unroll
            for (int j = 0; j < 16; ++j) sY[j * EPB + tid] = 0.0f;
            sIdx[tid] = 0;
            sIdx[EPB + tid] = -1;
        }
    }

    const int lane = tid & 31, gid = lane >> 2, tig = lane & 3;
    const int wy = (tid >> 5) & 3;   // e-tile (4)
    const int wx = tid >> 7;         // o'-tile (2)
    float acc[2][4][4];
#pragma unroll
    for (int mt = 0; mt < 2; ++mt)
#pragma unroll
        for (int nt = 0; nt < 4; ++nt)
#pragma unroll
            for (int r = 0; r < 4; ++r) acc[mt][nt][r] = 0.0f;
    __syncthreads();

    for (int g = 0; g < 4; ++g) {
        const int nc = 2 * g + 1, i0 = g * g;
        for (int half = 0; half < 2; ++half) {
            // gather sSrc[ic][e][hh]  (prev chunk's U-phase already synced past)
            for (int idx = tid; idx < EPB * 32; idx += NTHREADS) {
                int e = idx >> 5, hh = idx & 31;
                int valid = sIdx[EPB + e] >= 0;
                const float* base =
                    nf + (size_t)sIdx[e] * 1024 + (half * 32 + hh) * 16 + i0;
#pragma unroll
                for (int ic = 0; ic < 7; ++ic)
                    if (ic < nc)
                        sSrc[(ic * EPB + e) * 32 + hh] =
                            valid ? __ldg(base + ic) : 0.0f;
            }

            const int qend = cGQ0[g + 1];
            for (int qb = cGQ0[g]; qb < qend; qb += 2) {
                const int nqc = (qend - qb >= 2) ? 2 : 1;
                __syncthreads();  // prior mma done reading sU/sM; sSrc visible

                // phase A: A coefficients + M tile copy (padded stride 68)
                for (int idx = tid; idx < nqc * nc * EPB; idx += NTHREADS) {
                    int e = idx & 127, r = idx >> 7;
                    int ic = r % nc, qq = r / nc, q = qb + qq;
                    int j0 = cQJ0[q], kg = cQKG[q];
                    int nj = (j0 == 0) ? 1 : (j0 == 1) ? 3 : (j0 == 4) ? 5 : 7;
                    const float* cgp = cg + (i0 + ic) * 256 + j0 * 16 + kg;
                    float a = 0.0f;
#pragma unroll
                    for (int jc = 0; jc < 7; ++jc)
                        if (jc < nj) a += sY[(j0 + jc) * EPB + e] * __ldg(cgp + jc * 16);
                    sA[(qq * 7 + ic) * EPB + e] = a;
                }
                for (int idx = tid; idx < nqc * 512; idx += NTHREADS) {
                    int qq = idx >> 9, w = idx & 511;
                    int h = w >> 4, o4 = w & 15;
                    float4 v = ((const float4*)(g_M + (qb + qq) * 4096 +
                                                (half * 32 + h) * 64))[o4];
                    *(float4*)(sM + qq * 2176 + h * 68 + o4 * 4) = v;
                }
                __syncthreads();

                // phase B: U tiles (tf32-rounded), padded stride 36
                const float4* s4 = (const float4*)sSrc;
                for (int idx = tid; idx < EPB * 8; idx += NTHREADS) {
                    int e = idx >> 3, hv = idx & 7;
                    float4 u0 = {0, 0, 0, 0}, u1 = {0, 0, 0, 0};
#pragma unroll
                    for (int ic = 0; ic < 7; ++ic)
                        if (ic < nc) {
                            float4 s = s4[(ic * EPB + e) * 8 + hv];
                            float a0 = sA[ic * EPB + e];
                            u0.x += a0 * s.x; u0.y += a0 * s.y;
                            u0.z += a0 * s.z; u0.w += a0 * s.w;
                            if (nqc == 2) {
                                float a1 = sA[(7 + ic) * EPB + e];
                                u1.x += a1 * s.x; u1.y += a1 * s.y;
                                u1.z += a1 * s.z; u1.w += a1 * s.w;
                            }
                        }
                    uint4 t0 = {tf32r(u0.x), tf32r(u0.y), tf32r(u0.z), tf32r(u0.w)};
                    *(uint4*)(sU + e * 36 + hv * 4) = t0;
                    if (nqc == 2) {
                        uint4 t1 = {tf32r(u1.x), tf32r(u1.y), tf32r(u1.z), tf32r(u1.w)};
                        *(uint4*)(sU + 4608 + e * 36 + hv * 4) = t1;
                    }
                }
                __syncthreads();

                // mma phase: per warp 32x32 tile, K = nqc*32
                for (int qq = 0; qq < nqc; ++qq) {
                    const float* Ub = sU + qq * 4608;
                    const float* Mb = sM + qq * 2176;
#pragma unroll
                    for (int ks = 0; ks < 4; ++ks) {
                        const int k0 = ks * 8;
                        uint32_t a[2][4];
#pragma unroll
                        for (int mt = 0; mt < 2; ++mt) {
                            const float* up =
                                Ub + (wy * 32 + mt * 16 + gid) * 36 + k0 + tig;
                            a[mt][0] = __float_as_uint(up[0]);
                            a[mt][1] = __float_as_uint(up[8 * 36]);
                            a[mt][2] = __float_as_uint(up[4]);
                            a[mt][3] = __float_as_uint(up[8 * 36 + 4]);
                        }
#pragma unroll
                        for (int nt = 0; nt < 4; ++nt) {
                            const float* mp =
                                Mb + (k0 + tig) * 68 + wx * 32 + nt * 8 + gid;
                            uint32_t b0 = __float_as_uint(mp[0]);
                            uint32_t b1 = __float_as_uint(mp[4 * 68]);
                            mma8(acc[0][nt], a[0], b0, b1);
                            mma8(acc[1][nt], a[1], b0, b1);
                        }
                    }
                }
            }
        }
    }

    // ---- epilogue: float2 atomics into out[dst] ----
#pragma unroll
    for (int mt = 0; mt < 2; ++mt)
#pragma unroll
        for (int r = 0; r < 2; ++r) {
            int e = wy * 32 + mt * 16 + gid + r * 8;
            int dst = sIdx[EPB + e];
            if (dst >= 0) {
                float* op = out + (size_t)dst * 64 + wx * 32 + 2 * tig;
#pragma unroll
                for (int nt = 0; nt < 4; ++nt) {
                    float2 v = make_float2(acc[mt][nt][r * 2],
                                           acc[mt][nt][r * 2 + 1]);
                    atomicAdd((float2*)(op + nt * 8), v);
                }
            }
        }
}

// ---------------------------------------------------------------------------
extern "C" void kernel_launch(void* const* d_in, const int* in_sizes, int n_in,
                              void* d_out, int out_size) {
    const float* nf = (const float*)d_in[0];
    const float* ev = (const float*)d_in[1];
    const int* ei = (const int*)d_in[2];
    const float* cg = (const float*)d_in[3];
    const float* tw = (const float*)d_in[4];
    const float* wlin = (const float*)d_in[5];
    const float* bl = (const float*)d_in[6];
    float* out = (float*)d_out;
    const int E = in_sizes[1] / 3;
    const int N = in_sizes[0] / 1024;

    cudaFuncSetAttribute(edge_kernel,
                         cudaFuncAttributeMaxDynamicSharedMemorySize, SMEM_TOTAL);
    build_M_kernel<<<Q_TOTAL, 256>>>(tw, wlin);
    init_out_kernel<<<(N * 64 + 255) / 256, 256>>>(out, bl, N * 64);
    edge_kernel<<<(E + EPB - 1) / EPB, NTHREADS, SMEM_TOTAL>>>(nf, ev, ei, cg, out, E);
}